// round 1
// baseline (speedup 1.0000x reference)
#include <cuda_runtime.h>
#include <cuda_bf16.h>
#include <math.h>

// Problem constants
#define BATCH    256
#define NREG     36
#define NWORD    60
#define IMG_DIM  2048
#define WORD_DIM 300
#define EMBED    1024
#define LAMBDA_SM 9.0f

// ---------------- scratch (device globals; no allocation allowed) ----------------
__device__ float g_img_embs[BATCH * NREG  * EMBED];   // (256*36, 1024)
__device__ float g_cap_embs[BATCH * NWORD * EMBED];   // (256*60, 1024)
__device__ float g_S[BATCH * NWORD * NREG];           // sim (b,l,r)
__device__ float g_G[BATCH * NREG  * NREG];           // gram (b,r,r')

// ---------------- SGEMM: C[M,N] = A[M,K] @ B[K,N] + bias[N] ----------------
// A row-major, B row-major. M%128==0, N%128==0 required. K arbitrary (guarded).
#define BM 128
#define BN 128
#define BK 16
#define TM 8
#define TN 8

__global__ __launch_bounds__(256)
void sgemm_bias(const float* __restrict__ A, const float* __restrict__ B,
                const float* __restrict__ bias, float* __restrict__ C,
                int M, int N, int K)
{
    __shared__ float As[BK][BM];   // transposed A tile
    __shared__ float Bs[BK][BN];

    const int tid  = threadIdx.x;
    const int brow = blockIdx.y;
    const int bcol = blockIdx.x;
    const int trow = tid >> 4;     // 0..15
    const int tcol = tid & 15;     // 0..15

    float acc[TM][TN];
    #pragma unroll
    for (int i = 0; i < TM; i++)
        #pragma unroll
        for (int j = 0; j < TN; j++) acc[i][j] = 0.f;

    const float* Ablk = A + (size_t)brow * BM * K;
    const float* Bblk = B + (size_t)bcol * BN;

    // A-load coords: 2 float4 per thread
    const int a_r0 = tid >> 2;           // 0..63
    const int a_c  = (tid & 3) << 2;     // 0,4,8,12
    // B-load coords: 2 float4 per thread
    const int b_r0 = tid >> 5;           // 0..7
    const int b_c  = (tid & 31) << 2;    // 0..124

    for (int k0 = 0; k0 < K; k0 += BK) {
        // ---- load A tile (BM x BK), store transposed ----
        #pragma unroll
        for (int i = 0; i < 2; i++) {
            int r  = a_r0 + i * 64;
            int gk = k0 + a_c;
            float4 v;
            if (gk + 3 < K) {
                v = *(const float4*)(Ablk + (size_t)r * K + gk);
            } else {
                float t[4];
                #pragma unroll
                for (int j = 0; j < 4; j++)
                    t[j] = (gk + j < K) ? Ablk[(size_t)r * K + gk + j] : 0.f;
                v = make_float4(t[0], t[1], t[2], t[3]);
            }
            As[a_c + 0][r] = v.x;
            As[a_c + 1][r] = v.y;
            As[a_c + 2][r] = v.z;
            As[a_c + 3][r] = v.w;
        }
        // ---- load B tile (BK x BN) ----
        #pragma unroll
        for (int i = 0; i < 2; i++) {
            int r  = b_r0 + i * 8;
            int gk = k0 + r;
            float4 v = make_float4(0.f, 0.f, 0.f, 0.f);
            if (gk < K) v = *(const float4*)(Bblk + (size_t)gk * N + b_c);
            *(float4*)&Bs[r][b_c] = v;
        }
        __syncthreads();

        #pragma unroll
        for (int kk = 0; kk < BK; kk++) {
            float a_frag[TM], b_frag[TN];
            #pragma unroll
            for (int i = 0; i < TM; i++) a_frag[i] = As[kk][trow * TM + i];
            #pragma unroll
            for (int j = 0; j < TN; j++) b_frag[j] = Bs[kk][tcol * TN + j];
            #pragma unroll
            for (int i = 0; i < TM; i++)
                #pragma unroll
                for (int j = 0; j < TN; j++)
                    acc[i][j] += a_frag[i] * b_frag[j];
        }
        __syncthreads();
    }

    // ---- epilogue: + bias, store ----
    #pragma unroll
    for (int i = 0; i < TM; i++) {
        int row = brow * BM + trow * TM + i;
        #pragma unroll
        for (int j = 0; j < TN; j += 4) {
            int col = bcol * BN + tcol * TN + j;
            float4 v;
            v.x = acc[i][j + 0] + bias[col + 0];
            v.y = acc[i][j + 1] + bias[col + 1];
            v.z = acc[i][j + 2] + bias[col + 2];
            v.w = acc[i][j + 3] + bias[col + 3];
            *(float4*)(C + (size_t)row * N + col) = v;
        }
    }
}

// ---------------- row-wise l2 normalize (D = EMBED = 1024) ----------------
__global__ __launch_bounds__(256)
void l2norm_rows(float* __restrict__ X)
{
    const int row = blockIdx.x;
    float4* x = (float4*)(X + (size_t)row * EMBED);
    const int i = threadIdx.x;          // exactly 256 float4 per row
    float4 v = x[i];
    float ss = v.x * v.x + v.y * v.y + v.z * v.z + v.w * v.w;

    __shared__ float red[8];
    #pragma unroll
    for (int o = 16; o > 0; o >>= 1) ss += __shfl_xor_sync(0xffffffffu, ss, o);
    if ((i & 31) == 0) red[i >> 5] = ss;
    __syncthreads();
    if (i < 8) {
        float t = red[i];
        #pragma unroll
        for (int o = 4; o > 0; o >>= 1) t += __shfl_xor_sync(0xffu, t, o);
        if (i == 0) red[0] = 1.f / sqrtf(t + 1e-12f);
    }
    __syncthreads();
    const float s = red[0];
    v.x *= s; v.y *= s; v.z *= s; v.w *= s;
    x[i] = v;
}

// ---------------- per-batch sim (60x36) and Gram (36x36) ----------------
// Left rows: 0..59 = cap_embs[b], 60..95 = img_embs[b].  Right cols: img_embs[b].
// S[b,l,r] = cap_l . img_r ; G[b,r,r'] = img_r . img_r'
#define SG_BD 32
__global__ __launch_bounds__(256)
void sim_gram(const float* __restrict__ cap, const float* __restrict__ img,
              float* __restrict__ S, float* __restrict__ G)
{
    const int b   = blockIdx.x;
    const int tid = threadIdx.x;
    const int trow = tid >> 4;   // 0..15 -> rows trow*6..+5  (96 rows)
    const int tcol = tid & 15;   // 0..15 -> cols tcol*3..+2  (48 padded)

    __shared__ float Ls[SG_BD][97];   // [kd][row], stride 97 (conflict-free)
    __shared__ float Rs[SG_BD][49];   // [kd][col], stride 49; cols 36..47 zero

    // zero Rs padding once
    for (int i = tid; i < SG_BD * 49; i += 256)
        ((float*)Rs)[i] = 0.f;
    __syncthreads();

    const float* capb = cap + (size_t)b * NWORD * EMBED;
    const float* imgb = img + (size_t)b * NREG  * EMBED;

    float acc[6][3];
    #pragma unroll
    for (int i = 0; i < 6; i++)
        #pragma unroll
        for (int j = 0; j < 3; j++) acc[i][j] = 0.f;

    for (int d0 = 0; d0 < EMBED; d0 += SG_BD) {
        // load left (96 rows x 32): 3072 = 12 * 256
        #pragma unroll
        for (int it = 0; it < 12; it++) {
            int idx = tid + it * 256;
            int row = idx >> 5;
            int kd  = idx & 31;
            float v;
            if (row < NWORD) v = capb[(size_t)row * EMBED + d0 + kd];
            else             v = imgb[(size_t)(row - NWORD) * EMBED + d0 + kd];
            Ls[kd][row] = v;
        }
        // load right (36 x 32): 1152 entries
        for (int idx = tid; idx < NREG * SG_BD; idx += 256) {
            int row = idx >> 5;
            int kd  = idx & 31;
            Rs[kd][row] = imgb[(size_t)row * EMBED + d0 + kd];
        }
        __syncthreads();

        #pragma unroll
        for (int kd = 0; kd < SG_BD; kd++) {
            float a[6], r[3];
            #pragma unroll
            for (int i = 0; i < 6; i++) a[i] = Ls[kd][trow * 6 + i];
            #pragma unroll
            for (int j = 0; j < 3; j++) r[j] = Rs[kd][tcol * 3 + j];
            #pragma unroll
            for (int i = 0; i < 6; i++)
                #pragma unroll
                for (int j = 0; j < 3; j++)
                    acc[i][j] += a[i] * r[j];
        }
        __syncthreads();
    }

    // write out
    #pragma unroll
    for (int i = 0; i < 6; i++) {
        int row = trow * 6 + i;
        #pragma unroll
        for (int j = 0; j < 3; j++) {
            int col = tcol * 3 + j;
            if (col < NREG) {
                if (row < NWORD)
                    S[((size_t)b * NWORD + row) * NREG + col] = acc[i][j];
                else
                    G[((size_t)b * NREG + (row - NWORD)) * NREG + col] = acc[i][j];
            }
        }
    }
}

// ---------------- softmax + cosine + masked mean ----------------
// Per word l:  w = softmax(9*s),  num = sum w_r s_r,  |att| = sqrt(w^T G w)
// r_l = num / (max(1,eps) * max(|att|,eps));  out[b] = sum_{l<len} r_l / len
__global__ __launch_bounds__(256)
void attn_final(const float* __restrict__ S, const float* __restrict__ G,
                const int* __restrict__ lens, float* __restrict__ out)
{
    const int b   = blockIdx.x;
    const int tid = threadIdx.x;
    const int warp = tid >> 5, lane = tid & 31;

    __shared__ float sS[NWORD][NREG];
    __shared__ float sG[NREG][37];      // padded
    __shared__ float sW[8][NREG];
    __shared__ float wsum[8];

    for (int i = tid; i < NWORD * NREG; i += 256)
        sS[i / NREG][i % NREG] = S[(size_t)b * NWORD * NREG + i];
    for (int i = tid; i < NREG * NREG; i += 256)
        sG[i / NREG][i % NREG] = G[(size_t)b * NREG * NREG + i];
    __syncthreads();

    const int len = lens[b];
    float partial = 0.f;

    for (int l = warp; l < len; l += 8) {
        float s0 = sS[l][lane];
        float s1 = (lane < 4) ? sS[l][lane + 32] : -1e30f;
        float m = fmaxf(s0, s1);
        #pragma unroll
        for (int o = 16; o > 0; o >>= 1) m = fmaxf(m, __shfl_xor_sync(0xffffffffu, m, o));

        float e0 = expf(LAMBDA_SM * (s0 - m));
        float e1 = (lane < 4) ? expf(LAMBDA_SM * (s1 - m)) : 0.f;
        float Z = e0 + e1;
        #pragma unroll
        for (int o = 16; o > 0; o >>= 1) Z += __shfl_xor_sync(0xffffffffu, Z, o);
        float inv = 1.f / Z;
        float w0 = e0 * inv;
        float w1 = e1 * inv;

        sW[warp][lane] = w0;
        if (lane < 4) sW[warp][lane + 32] = w1;
        __syncwarp();

        float num = w0 * s0 + ((lane < 4) ? w1 * s1 : 0.f);
        #pragma unroll
        for (int o = 16; o > 0; o >>= 1) num += __shfl_xor_sync(0xffffffffu, num, o);

        // den2 = w^T G w
        float t0 = 0.f;
        #pragma unroll
        for (int rp = 0; rp < NREG; rp++) t0 += sW[warp][rp] * sG[lane][rp];
        float den2 = w0 * t0;
        if (lane < 4) {
            float t1 = 0.f;
            #pragma unroll
            for (int rp = 0; rp < NREG; rp++) t1 += sW[warp][rp] * sG[lane + 32][rp];
            den2 += w1 * t1;
        }
        #pragma unroll
        for (int o = 16; o > 0; o >>= 1) den2 += __shfl_xor_sync(0xffffffffu, den2, o);

        float den = fmaxf(sqrtf(den2), 1e-8f);  // ||att|| clamp; ||cap||==1
        partial += num / den;
        __syncwarp();
    }

    if (lane == 0) wsum[warp] = partial;
    __syncthreads();
    if (tid == 0) {
        float tot = 0.f;
        #pragma unroll
        for (int w = 0; w < 8; w++) tot += wsum[w];
        out[b] = tot / (float)len;
    }
}

// ---------------- launcher ----------------
extern "C" void kernel_launch(void* const* d_in, const int* in_sizes, int n_in,
                              void* d_out, int out_size)
{
    const float* images      = (const float*)d_in[0];
    const float* captions    = (const float*)d_in[1];
    const int*   cap_lengths = (const int*)  d_in[2];
    const float* W_img       = (const float*)d_in[3];
    const float* b_img       = (const float*)d_in[4];
    const float* W_txt       = (const float*)d_in[5];
    const float* b_txt       = (const float*)d_in[6];
    float* out = (float*)d_out;

    float *img_embs, *cap_embs, *Sbuf, *Gbuf;
    cudaGetSymbolAddress((void**)&img_embs, g_img_embs);
    cudaGetSymbolAddress((void**)&cap_embs, g_cap_embs);
    cudaGetSymbolAddress((void**)&Sbuf, g_S);
    cudaGetSymbolAddress((void**)&Gbuf, g_G);

    // Encoders
    sgemm_bias<<<dim3(EMBED / BN, (BATCH * NREG) / BM), 256>>>(
        images, W_img, b_img, img_embs, BATCH * NREG, EMBED, IMG_DIM);
    sgemm_bias<<<dim3(EMBED / BN, (BATCH * NWORD) / BM), 256>>>(
        captions, W_txt, b_txt, cap_embs, BATCH * NWORD, EMBED, WORD_DIM);

    // L2 normalize
    l2norm_rows<<<BATCH * NREG, 256>>>(img_embs);
    l2norm_rows<<<BATCH * NWORD, 256>>>(cap_embs);

    // sim + gram per batch
    sim_gram<<<BATCH, 256>>>(cap_embs, img_embs, Sbuf, Gbuf);

    // softmax + cosine + masked mean
    attn_final<<<BATCH, 256>>>(Sbuf, Gbuf, cap_lengths, out);
}

// round 3
// speedup vs baseline: 4.1803x; 4.1803x over previous
#include <cuda_runtime.h>
#include <cuda_fp16.h>
#include <math.h>
#include <stdint.h>

// ---------------- problem constants ----------------
#define BATCH    256
#define NREG     36
#define NWORD    60
#define IMG_DIM  2048
#define WORD_DIM 300
#define KPAD_TXT 320
#define EMBED    1024
#define LAMBDA_SM 9.0f
#define M_IMG (BATCH*NREG)     // 9216
#define M_CAP (BATCH*NWORD)    // 15360

// ---------------- scratch (device globals; no allocation allowed) ----------------
__device__ __align__(256) float g_img_embs[M_IMG * EMBED];
__device__ __align__(256) float g_cap_embs[M_CAP * EMBED];
__device__ __align__(256) float g_S[BATCH * NWORD * NREG];
__device__ __align__(256) float g_G[BATCH * NREG  * NREG];

__device__ __align__(256) __half g_A16_img[M_IMG * IMG_DIM];
__device__ __align__(256) __half g_A16_cap[M_CAP * KPAD_TXT];
__device__ __align__(256) __half g_W16_img[IMG_DIM * EMBED];
__device__ __align__(256) __half g_W16_txt[KPAD_TXT * EMBED];

// ---------------- PTX helpers (all sm_80-level; no arch-specific ops) ----------------
__device__ __forceinline__ uint32_t s2u(const void* p) {
    uint32_t a;
    asm("{ .reg .u64 t; cvta.to.shared.u64 t, %1; cvt.u32.u64 %0, t; }" : "=r"(a) : "l"(p));
    return a;
}
__device__ __forceinline__ void cp16(uint32_t s, const void* g) {
    asm volatile("cp.async.cg.shared.global [%0], [%1], 16;" :: "r"(s), "l"(g));
}
#define CP_COMMIT() asm volatile("cp.async.commit_group;" ::: "memory")

#define LDSM_X4(r0, r1, r2, r3, addr)                                            \
    asm volatile("ldmatrix.sync.aligned.m8n8.x4.shared.b16 {%0,%1,%2,%3}, [%4];" \
                 : "=r"(r0), "=r"(r1), "=r"(r2), "=r"(r3) : "r"(addr))
#define LDSM_X4_T(r0, r1, r2, r3, addr)                                          \
    asm volatile("ldmatrix.sync.aligned.m8n8.x4.trans.shared.b16 {%0,%1,%2,%3}, [%4];" \
                 : "=r"(r0), "=r"(r1), "=r"(r2), "=r"(r3) : "r"(addr))

#define MMA16816(d, a, b0, b1)                                                   \
    asm volatile("mma.sync.aligned.m16n8k16.row.col.f32.f16.f16.f32 "            \
                 "{%0,%1,%2,%3}, {%4,%5,%6,%7}, {%8,%9}, {%0,%1,%2,%3};"         \
                 : "+f"((d)[0]), "+f"((d)[1]), "+f"((d)[2]), "+f"((d)[3])        \
                 : "r"((a)[0]), "r"((a)[1]), "r"((a)[2]), "r"((a)[3]),           \
                   "r"(b0), "r"(b1))

// ---------------- convert kernels ----------------
__global__ void cvt_f32_f16(const float4* __restrict__ X, __half2* __restrict__ Y, int n4)
{
    int i = blockIdx.x * blockDim.x + threadIdx.x;
    if (i >= n4) return;
    float4 v = X[i];
    Y[2 * i]     = __floats2half2_rn(v.x, v.y);
    Y[2 * i + 1] = __floats2half2_rn(v.z, v.w);
}

// captions (M_CAP, 300) f32 -> (M_CAP, 320) f16 zero-padded
__global__ void cvt_pad_cap(const float* __restrict__ X, __half2* __restrict__ Y)
{
    int idx = blockIdx.x * blockDim.x + threadIdx.x;   // over M_CAP * 80 groups of 4
    if (idx >= M_CAP * 80) return;
    int row = idx / 80, g = idx - row * 80;
    __half2 h0, h1;
    if (g < 75) {
        float4 v = *(const float4*)(X + (size_t)row * WORD_DIM + g * 4);
        h0 = __floats2half2_rn(v.x, v.y);
        h1 = __floats2half2_rn(v.z, v.w);
    } else {
        h0 = __floats2half2_rn(0.f, 0.f);
        h1 = h0;
    }
    size_t o = ((size_t)row * KPAD_TXT + g * 4) >> 1;
    Y[o] = h0; Y[o + 1] = h1;
}

// W_txt (300, 1024) f32 -> (320, 1024) f16 zero-padded rows
__global__ void cvt_pad_wtxt(const float* __restrict__ W, __half2* __restrict__ Y)
{
    int idx = blockIdx.x * blockDim.x + threadIdx.x;   // over 320*256 groups of 4
    if (idx >= KPAD_TXT * 256) return;
    int row = idx >> 8, g = idx & 255;
    __half2 h0, h1;
    if (row < WORD_DIM) {
        float4 v = *(const float4*)(W + (size_t)row * EMBED + g * 4);
        h0 = __floats2half2_rn(v.x, v.y);
        h1 = __floats2half2_rn(v.z, v.w);
    } else {
        h0 = __floats2half2_rn(0.f, 0.f);
        h1 = h0;
    }
    size_t o = ((size_t)row * EMBED + g * 4) >> 1;
    Y[o] = h0; Y[o + 1] = h1;
}

// ---------------- fp16 tensor-core GEMM: C[M,N] = A[M,K] @ W[K,N] + bias ----------------
// A (M,K) f16 row-major; W (K,N) f16 row-major; C f32. M%128==0, N%128==0, K%32==0.
#define GBM 128
#define GBN 128
#define GBK 32
#define STAGES 3
#define STG_A 8192
#define STG_B 8192
#define STG_BYTES (STG_A + STG_B)
#define GEMM_SMEM (STAGES * STG_BYTES)   // 49152

// swizzled smem offsets (conflict-free for both cp.async and ldmatrix)
__device__ __forceinline__ uint32_t aoff(int m, int u) {        // u = k/8 in [0,4)
    int blk  = m >> 1;
    int u128 = ((m & 1) << 2) | u;
    return (uint32_t)((blk << 7) + (((u128 ^ (blk & 7)) << 4)));
}
__device__ __forceinline__ uint32_t boff(int k, int j) {        // j = n/8 in [0,16)
    return (uint32_t)((k << 8) + ((j >> 3) << 7) + (((j & 7) ^ (k & 7)) << 4));
}

__global__ __launch_bounds__(256, 2)
void gemm_f16(const __half* __restrict__ A, const __half* __restrict__ W,
              const float* __restrict__ bias, float* __restrict__ C,
              int N, int K)
{
    extern __shared__ char smem[];
    const uint32_t sbase = s2u(smem);
    const int tid  = threadIdx.x;
    const int lane = tid & 31;
    const int wid  = tid >> 5;
    const int wm   = (wid & 1) * 64;
    const int wn   = (wid >> 1) * 32;
    const int mbase = blockIdx.y * GBM;
    const int nbase = blockIdx.x * GBN;
    const int nk = K / GBK;

    float d[4][4][4];
    #pragma unroll
    for (int i = 0; i < 4; i++)
        #pragma unroll
        for (int j = 0; j < 4; j++)
            #pragma unroll
            for (int q = 0; q < 4; q++) d[i][j][q] = 0.f;

    auto load_slab = [&](int t, int st) {
        const uint32_t sA = sbase + st * STG_BYTES;
        const uint32_t sB = sA + STG_A;
        const int kb = t * GBK;
        #pragma unroll
        for (int i = 0; i < 2; i++) {
            int c = tid + i * 256;          // 512 chunks of A
            int m = c >> 2, u = c & 3;
            cp16(sA + aoff(m, u), A + (size_t)(mbase + m) * K + kb + u * 8);
        }
        #pragma unroll
        for (int i = 0; i < 2; i++) {
            int c = tid + i * 256;          // 512 chunks of B
            int k = c >> 4, j = c & 15;
            cp16(sB + boff(k, j), W + (size_t)(kb + k) * N + nbase + j * 8);
        }
        CP_COMMIT();
    };

    load_slab(0, 0);
    load_slab(1, 1);

    for (int s = 0; s < nk; s++) {
        if (s + 1 < nk) asm volatile("cp.async.wait_group 1;" ::: "memory");
        else            asm volatile("cp.async.wait_group 0;" ::: "memory");
        __syncthreads();
        if (s + 2 < nk) load_slab(s + 2, (s + 2) % STAGES);

        const uint32_t sA = sbase + (s % STAGES) * STG_BYTES;
        const uint32_t sB = sA + STG_A;
        #pragma unroll
        for (int ks = 0; ks < 2; ks++) {
            uint32_t a[4][4], bb[2][4];
            #pragma unroll
            for (int mi = 0; mi < 4; mi++) {
                int m = wm + mi * 16 + (lane & 15);
                int u = ks * 2 + (lane >> 4);
                LDSM_X4(a[mi][0], a[mi][1], a[mi][2], a[mi][3], sA + aoff(m, u));
            }
            #pragma unroll
            for (int p = 0; p < 2; p++) {
                int k = ks * 16 + (lane & 7) + ((lane >> 3) & 1) * 8;
                int j = ((wn + p * 16) >> 3) + (lane >> 4);
                LDSM_X4_T(bb[p][0], bb[p][1], bb[p][2], bb[p][3], sB + boff(k, j));
            }
            #pragma unroll
            for (int mi = 0; mi < 4; mi++)
                #pragma unroll
                for (int nj = 0; nj < 4; nj++)
                    MMA16816(d[mi][nj], a[mi], bb[nj >> 1][(nj & 1) * 2],
                                               bb[nj >> 1][(nj & 1) * 2 + 1]);
        }
    }

    // epilogue: + bias, f32 store
    #pragma unroll
    for (int mi = 0; mi < 4; mi++) {
        int r0 = mbase + wm + mi * 16 + (lane >> 2);
        #pragma unroll
        for (int nj = 0; nj < 4; nj++) {
            int cc = nbase + wn + nj * 8 + ((lane & 3) << 1);
            float2 bv = *(const float2*)(bias + cc);
            float2 o0, o1;
            o0.x = d[mi][nj][0] + bv.x; o0.y = d[mi][nj][1] + bv.y;
            o1.x = d[mi][nj][2] + bv.x; o1.y = d[mi][nj][3] + bv.y;
            *(float2*)(C + (size_t)r0 * N + cc)       = o0;
            *(float2*)(C + (size_t)(r0 + 8) * N + cc) = o1;
        }
    }
}

// ---------------- per-batch sim (60x36) and Gram (36x36), with fused l2norm ----------
// Inputs are UN-normalized embeddings; normalization (rsqrt(ss+1e-12)) is folded in.
#define SG_BD 32
__global__ __launch_bounds__(256)
void sim_gram(const float* __restrict__ cap, const float* __restrict__ img,
              float* __restrict__ S, float* __restrict__ G)
{
    const int b   = blockIdx.x;
    const int tid = threadIdx.x;
    const int warp = tid >> 5, lane = tid & 31;
    const int trow = tid >> 4;
    const int tcol = tid & 15;

    __shared__ float Ls[SG_BD][97];
    __shared__ float Rs[SG_BD][49];
    __shared__ float sinv[96];

    for (int i = tid; i < SG_BD * 49; i += 256)
        ((float*)Rs)[i] = 0.f;
    __syncthreads();

    const float* capb = cap + (size_t)b * NWORD * EMBED;
    const float* imgb = img + (size_t)b * NREG  * EMBED;

    float acc[6][3];
    #pragma unroll
    for (int i = 0; i < 6; i++)
        #pragma unroll
        for (int j = 0; j < 3; j++) acc[i][j] = 0.f;

    float sq[12];
    #pragma unroll
    for (int i = 0; i < 12; i++) sq[i] = 0.f;

    for (int d0 = 0; d0 < EMBED; d0 += SG_BD) {
        #pragma unroll
        for (int it = 0; it < 12; it++) {
            int idx = tid + it * 256;
            int row = idx >> 5;              // == warp + 8*it
            int kd  = idx & 31;              // == lane
            float v;
            if (row < NWORD) v = capb[(size_t)row * EMBED + d0 + kd];
            else             v = imgb[(size_t)(row - NWORD) * EMBED + d0 + kd];
            Ls[kd][row] = v;
            sq[it] += v * v;
        }
        for (int idx = tid; idx < NREG * SG_BD; idx += 256) {
            int row = idx >> 5;
            int kd  = idx & 31;
            Rs[kd][row] = imgb[(size_t)row * EMBED + d0 + kd];
        }
        __syncthreads();

        #pragma unroll
        for (int kd = 0; kd < SG_BD; kd++) {
            float a[6], r[3];
            #pragma unroll
            for (int i = 0; i < 6; i++) a[i] = Ls[kd][trow * 6 + i];
            #pragma unroll
            for (int j = 0; j < 3; j++) r[j] = Rs[kd][tcol * 3 + j];
            #pragma unroll
            for (int i = 0; i < 6; i++)
                #pragma unroll
                for (int j = 0; j < 3; j++)
                    acc[i][j] += a[i] * r[j];
        }
        __syncthreads();
    }

    // row sum-of-squares -> inverse norms
    #pragma unroll
    for (int it = 0; it < 12; it++) {
        float t = sq[it];
        #pragma unroll
        for (int o = 16; o > 0; o >>= 1) t += __shfl_xor_sync(0xffffffffu, t, o);
        if (lane == 0) sinv[warp + 8 * it] = t;
    }
    __syncthreads();
    if (tid < 96) sinv[tid] = rsqrtf(sinv[tid] + 1e-12f);
    __syncthreads();

    #pragma unroll
    for (int i = 0; i < 6; i++) {
        int row = trow * 6 + i;
        #pragma unroll
        for (int j = 0; j < 3; j++) {
            int col = tcol * 3 + j;
            if (col < NREG) {
                float v = acc[i][j] * sinv[row] * sinv[60 + col];
                if (row < NWORD)
                    S[((size_t)b * NWORD + row) * NREG + col] = v;
                else
                    G[((size_t)b * NREG + (row - NWORD)) * NREG + col] = v;
            }
        }
    }
}

// ---------------- softmax + cosine + masked mean ----------------
__global__ __launch_bounds__(256)
void attn_final(const float* __restrict__ S, const float* __restrict__ G,
                const int* __restrict__ lens, float* __restrict__ out)
{
    const int b   = blockIdx.x;
    const int tid = threadIdx.x;
    const int warp = tid >> 5, lane = tid & 31;

    __shared__ float sS[NWORD][NREG];
    __shared__ float sG[NREG][37];
    __shared__ float sW[8][NREG];
    __shared__ float wsum[8];

    for (int i = tid; i < NWORD * NREG; i += 256)
        sS[i / NREG][i % NREG] = S[(size_t)b * NWORD * NREG + i];
    for (int i = tid; i < NREG * NREG; i += 256)
        sG[i / NREG][i % NREG] = G[(size_t)b * NREG * NREG + i];
    __syncthreads();

    const int len = lens[b];
    float partial = 0.f;

    for (int l = warp; l < len; l += 8) {
        float s0 = sS[l][lane];
        float s1 = (lane < 4) ? sS[l][lane + 32] : -1e30f;
        float m = fmaxf(s0, s1);
        #pragma unroll
        for (int o = 16; o > 0; o >>= 1) m = fmaxf(m, __shfl_xor_sync(0xffffffffu, m, o));

        float e0 = expf(LAMBDA_SM * (s0 - m));
        float e1 = (lane < 4) ? expf(LAMBDA_SM * (s1 - m)) : 0.f;
        float Z = e0 + e1;
        #pragma unroll
        for (int o = 16; o > 0; o >>= 1) Z += __shfl_xor_sync(0xffffffffu, Z, o);
        float inv = 1.f / Z;
        float w0 = e0 * inv;
        float w1 = e1 * inv;

        sW[warp][lane] = w0;
        if (lane < 4) sW[warp][lane + 32] = w1;
        __syncwarp();

        float num = w0 * s0 + ((lane < 4) ? w1 * s1 : 0.f);
        #pragma unroll
        for (int o = 16; o > 0; o >>= 1) num += __shfl_xor_sync(0xffffffffu, num, o);

        float t0 = 0.f;
        #pragma unroll
        for (int rp = 0; rp < NREG; rp++) t0 += sW[warp][rp] * sG[lane][rp];
        float den2 = w0 * t0;
        if (lane < 4) {
            float t1 = 0.f;
            #pragma unroll
            for (int rp = 0; rp < NREG; rp++) t1 += sW[warp][rp] * sG[lane + 32][rp];
            den2 += w1 * t1;
        }
        #pragma unroll
        for (int o = 16; o > 0; o >>= 1) den2 += __shfl_xor_sync(0xffffffffu, den2, o);

        float den = fmaxf(sqrtf(den2), 1e-8f);
        partial += num / den;
        __syncwarp();
    }

    if (lane == 0) wsum[warp] = partial;
    __syncthreads();
    if (tid == 0) {
        float tot = 0.f;
        #pragma unroll
        for (int w = 0; w < 8; w++) tot += wsum[w];
        out[b] = tot / (float)len;
    }
}

// ---------------- launcher ----------------
extern "C" void kernel_launch(void* const* d_in, const int* in_sizes, int n_in,
                              void* d_out, int out_size)
{
    const float* images      = (const float*)d_in[0];
    const float* captions    = (const float*)d_in[1];
    const int*   cap_lengths = (const int*)  d_in[2];
    const float* W_img       = (const float*)d_in[3];
    const float* b_img       = (const float*)d_in[4];
    const float* W_txt       = (const float*)d_in[5];
    const float* b_txt       = (const float*)d_in[6];
    float* out = (float*)d_out;

    float *img_embs, *cap_embs, *Sbuf, *Gbuf;
    cudaGetSymbolAddress((void**)&img_embs, g_img_embs);
    cudaGetSymbolAddress((void**)&cap_embs, g_cap_embs);
    cudaGetSymbolAddress((void**)&Sbuf, g_S);
    cudaGetSymbolAddress((void**)&Gbuf, g_G);

    __half *A16I, *A16C, *W16I, *W16T;
    cudaGetSymbolAddress((void**)&A16I, g_A16_img);
    cudaGetSymbolAddress((void**)&A16C, g_A16_cap);
    cudaGetSymbolAddress((void**)&W16I, g_W16_img);
    cudaGetSymbolAddress((void**)&W16T, g_W16_txt);

    cudaFuncSetAttribute(gemm_f16, cudaFuncAttributeMaxDynamicSharedMemorySize, GEMM_SMEM);

    // converts
    {
        int n4 = (M_IMG * IMG_DIM) / 4;
        cvt_f32_f16<<<(n4 + 255) / 256, 256>>>((const float4*)images, (__half2*)A16I, n4);
    }
    {
        int n4 = (IMG_DIM * EMBED) / 4;
        cvt_f32_f16<<<(n4 + 255) / 256, 256>>>((const float4*)W_img, (__half2*)W16I, n4);
    }
    cvt_pad_cap<<<(M_CAP * 80 + 255) / 256, 256>>>(captions, (__half2*)A16C);
    cvt_pad_wtxt<<<(KPAD_TXT * 256 + 255) / 256, 256>>>(W_txt, (__half2*)W16T);

    // tensor-core encoder GEMMs
    gemm_f16<<<dim3(EMBED / GBN, M_IMG / GBM), 256, GEMM_SMEM>>>(
        A16I, W16I, b_img, img_embs, EMBED, IMG_DIM);
    gemm_f16<<<dim3(EMBED / GBN, M_CAP / GBM), 256, GEMM_SMEM>>>(
        A16C, W16T, b_txt, cap_embs, EMBED, KPAD_TXT);

    // sim + gram per batch (l2norm fused)
    sim_gram<<<BATCH, 256>>>(cap_embs, img_embs, Sbuf, Gbuf);

    // softmax + cosine + masked mean
    attn_final<<<BATCH, 256>>>(Sbuf, Gbuf, cap_lengths, out);
}

// round 4
// speedup vs baseline: 6.1784x; 1.4780x over previous
#include <cuda_runtime.h>
#include <cuda_fp16.h>
#include <math.h>
#include <stdint.h>

// ---------------- problem constants ----------------
#define BATCH    256
#define NREG     36
#define NWORD    60
#define IMG_DIM  2048
#define WORD_DIM 300
#define KPAD_TXT 320
#define EMBED    1024
#define LAMBDA_SM 9.0f
#define M_IMG (BATCH*NREG)     // 9216
#define M_CAP (BATCH*NWORD)    // 15360

// ---------------- scratch (device globals; no allocation allowed) ----------------
__device__ __align__(256) __half g_img_embs[M_IMG * EMBED];
__device__ __align__(256) __half g_cap_embs[M_CAP * EMBED];

__device__ __align__(256) __half g_A16_img[M_IMG * IMG_DIM];
__device__ __align__(256) __half g_A16_cap[M_CAP * KPAD_TXT];
__device__ __align__(256) __half g_W16_img[IMG_DIM * EMBED];
__device__ __align__(256) __half g_W16_txt[KPAD_TXT * EMBED];

// ---------------- PTX helpers (sm_80-level only) ----------------
__device__ __forceinline__ uint32_t s2u(const void* p) {
    uint32_t a;
    asm("{ .reg .u64 t; cvta.to.shared.u64 t, %1; cvt.u32.u64 %0, t; }" : "=r"(a) : "l"(p));
    return a;
}
__device__ __forceinline__ void cp16(uint32_t s, const void* g) {
    asm volatile("cp.async.cg.shared.global [%0], [%1], 16;" :: "r"(s), "l"(g));
}
#define CP_COMMIT() asm volatile("cp.async.commit_group;" ::: "memory")

#define LDSM_X4(r0, r1, r2, r3, addr)                                            \
    asm volatile("ldmatrix.sync.aligned.m8n8.x4.shared.b16 {%0,%1,%2,%3}, [%4];" \
                 : "=r"(r0), "=r"(r1), "=r"(r2), "=r"(r3) : "r"(addr))
#define LDSM_X4_T(r0, r1, r2, r3, addr)                                          \
    asm volatile("ldmatrix.sync.aligned.m8n8.x4.trans.shared.b16 {%0,%1,%2,%3}, [%4];" \
                 : "=r"(r0), "=r"(r1), "=r"(r2), "=r"(r3) : "r"(addr))

#define MMA16816(d, a, b0, b1)                                                   \
    asm volatile("mma.sync.aligned.m16n8k16.row.col.f32.f16.f16.f32 "            \
                 "{%0,%1,%2,%3}, {%4,%5,%6,%7}, {%8,%9}, {%0,%1,%2,%3};"         \
                 : "+f"((d)[0]), "+f"((d)[1]), "+f"((d)[2]), "+f"((d)[3])        \
                 : "r"((a)[0]), "r"((a)[1]), "r"((a)[2]), "r"((a)[3]),           \
                   "r"(b0), "r"(b1))

// ---------------- convert kernels ----------------
__global__ void cvt_f32_f16(const float4* __restrict__ X, __half2* __restrict__ Y, int n4)
{
    int i = blockIdx.x * blockDim.x + threadIdx.x;
    if (i >= n4) return;
    float4 v = X[i];
    Y[2 * i]     = __floats2half2_rn(v.x, v.y);
    Y[2 * i + 1] = __floats2half2_rn(v.z, v.w);
}

// captions (M_CAP, 300) f32 -> (M_CAP, 320) f16 zero-padded
__global__ void cvt_pad_cap(const float* __restrict__ X, __half2* __restrict__ Y)
{
    int idx = blockIdx.x * blockDim.x + threadIdx.x;
    if (idx >= M_CAP * 80) return;
    int row = idx / 80, g = idx - row * 80;
    __half2 h0, h1;
    if (g < 75) {
        float4 v = *(const float4*)(X + (size_t)row * WORD_DIM + g * 4);
        h0 = __floats2half2_rn(v.x, v.y);
        h1 = __floats2half2_rn(v.z, v.w);
    } else {
        h0 = __floats2half2_rn(0.f, 0.f);
        h1 = h0;
    }
    size_t o = ((size_t)row * KPAD_TXT + g * 4) >> 1;
    Y[o] = h0; Y[o + 1] = h1;
}

// W_txt (300, 1024) f32 -> (320, 1024) f16 zero-padded rows
__global__ void cvt_pad_wtxt(const float* __restrict__ W, __half2* __restrict__ Y)
{
    int idx = blockIdx.x * blockDim.x + threadIdx.x;
    if (idx >= KPAD_TXT * 256) return;
    int row = idx >> 8, g = idx & 255;
    __half2 h0, h1;
    if (row < WORD_DIM) {
        float4 v = *(const float4*)(W + (size_t)row * EMBED + g * 4);
        h0 = __floats2half2_rn(v.x, v.y);
        h1 = __floats2half2_rn(v.z, v.w);
    } else {
        h0 = __floats2half2_rn(0.f, 0.f);
        h1 = h0;
    }
    size_t o = ((size_t)row * EMBED + g * 4) >> 1;
    Y[o] = h0; Y[o + 1] = h1;
}

// ---------------- fp16 tensor-core GEMM: C[M,N] = A[M,K] @ W[K,N] + bias, f16 out ----
#define GBM 128
#define GBN 128
#define GBK 32
#define STAGES 3
#define STG_A 8192
#define STG_B 8192
#define STG_BYTES (STG_A + STG_B)
#define GEMM_SMEM (STAGES * STG_BYTES)   // 49152

__device__ __forceinline__ uint32_t aoff(int m, int u) {        // u = k/8 in [0,4)
    int blk  = m >> 1;
    int u128 = ((m & 1) << 2) | u;
    return (uint32_t)((blk << 7) + (((u128 ^ (blk & 7)) << 4)));
}
__device__ __forceinline__ uint32_t boff(int k, int j) {        // j = n/8 in [0,16)
    return (uint32_t)((k << 8) + ((j >> 3) << 7) + (((j & 7) ^ (k & 7)) << 4));
}

__global__ __launch_bounds__(256, 2)
void gemm_f16(const __half* __restrict__ A, const __half* __restrict__ W,
              const float* __restrict__ bias, __half* __restrict__ C,
              int N, int K)
{
    extern __shared__ char smem[];
    const uint32_t sbase = s2u(smem);
    const int tid  = threadIdx.x;
    const int lane = tid & 31;
    const int wid  = tid >> 5;
    const int wm   = (wid & 1) * 64;
    const int wn   = (wid >> 1) * 32;
    const int mbase = blockIdx.y * GBM;
    const int nbase = blockIdx.x * GBN;
    const int nk = K / GBK;

    float d[4][4][4];
    #pragma unroll
    for (int i = 0; i < 4; i++)
        #pragma unroll
        for (int j = 0; j < 4; j++)
            #pragma unroll
            for (int q = 0; q < 4; q++) d[i][j][q] = 0.f;

    auto load_slab = [&](int t, int st) {
        const uint32_t sA = sbase + st * STG_BYTES;
        const uint32_t sB = sA + STG_A;
        const int kb = t * GBK;
        #pragma unroll
        for (int i = 0; i < 2; i++) {
            int c = tid + i * 256;
            int m = c >> 2, u = c & 3;
            cp16(sA + aoff(m, u), A + (size_t)(mbase + m) * K + kb + u * 8);
        }
        #pragma unroll
        for (int i = 0; i < 2; i++) {
            int c = tid + i * 256;
            int k = c >> 4, j = c & 15;
            cp16(sB + boff(k, j), W + (size_t)(kb + k) * N + nbase + j * 8);
        }
        CP_COMMIT();
    };

    load_slab(0, 0);
    load_slab(1, 1);

    for (int s = 0; s < nk; s++) {
        if (s + 1 < nk) asm volatile("cp.async.wait_group 1;" ::: "memory");
        else            asm volatile("cp.async.wait_group 0;" ::: "memory");
        __syncthreads();
        if (s + 2 < nk) load_slab(s + 2, (s + 2) % STAGES);

        const uint32_t sA = sbase + (s % STAGES) * STG_BYTES;
        const uint32_t sB = sA + STG_A;
        #pragma unroll
        for (int ks = 0; ks < 2; ks++) {
            uint32_t a[4][4], bb[2][4];
            #pragma unroll
            for (int mi = 0; mi < 4; mi++) {
                int m = wm + mi * 16 + (lane & 15);
                int u = ks * 2 + (lane >> 4);
                LDSM_X4(a[mi][0], a[mi][1], a[mi][2], a[mi][3], sA + aoff(m, u));
            }
            #pragma unroll
            for (int p = 0; p < 2; p++) {
                int k = ks * 16 + (lane & 7) + ((lane >> 3) & 1) * 8;
                int j = ((wn + p * 16) >> 3) + (lane >> 4);
                LDSM_X4_T(bb[p][0], bb[p][1], bb[p][2], bb[p][3], sB + boff(k, j));
            }
            #pragma unroll
            for (int mi = 0; mi < 4; mi++)
                #pragma unroll
                for (int nj = 0; nj < 4; nj++)
                    MMA16816(d[mi][nj], a[mi], bb[nj >> 1][(nj & 1) * 2],
                                               bb[nj >> 1][(nj & 1) * 2 + 1]);
        }
    }

    // epilogue: + bias, f16 store
    #pragma unroll
    for (int mi = 0; mi < 4; mi++) {
        int r0 = mbase + wm + mi * 16 + (lane >> 2);
        #pragma unroll
        for (int nj = 0; nj < 4; nj++) {
            int cc = nbase + wn + nj * 8 + ((lane & 3) << 1);
            float2 bv = *(const float2*)(bias + cc);
            *(__half2*)(C + (size_t)r0 * N + cc) =
                __floats2half2_rn(d[mi][nj][0] + bv.x, d[mi][nj][1] + bv.y);
            *(__half2*)(C + (size_t)(r0 + 8) * N + cc) =
                __floats2half2_rn(d[mi][nj][2] + bv.x, d[mi][nj][3] + bv.y);
        }
    }
}

// ---------------- fused sim + gram + l2norm + softmax + cosine + mean ----------------
// One block per batch. A rows: 0..59 = cap, 60..95 = img (f16, K=1024).
// B rows: img (n-major). MMA computes raw dot products; row sumsq gives norms.
// Then in-smem softmax-attention epilogue produces out[b] directly.
#define SA_THREADS 192
#define SA_ROWS 112                // 96 data rows + 16 zero rows (n-padding)
#define SA_ROWB 128                // 64 halves per k-slab row
#define SA_BUF (SA_ROWS * SA_ROWB) // 14336
#define SA_NSLAB 16                // 1024 / 64
#define SSTRIDE 50
#define OFF_BUF  0
#define OFF_SS   (2 * SA_BUF)                    // 28672; 96 x 50 f32
#define OFF_SINV (OFF_SS + 96 * SSTRIDE * 4)     // 47872; 112 f32
#define OFF_SW   (OFF_SINV + 112 * 4)            // 48320; 6 x 40 f32
#define OFF_WSUM (OFF_SW + 6 * 40 * 4)           // 49280; 6 f32
#define SA_SMEM  (OFF_WSUM + 32)                 // 49312

__device__ __forceinline__ uint32_t soff_sa(int r, int c) {     // c in [0,8)
    return (uint32_t)(r * SA_ROWB + (((c ^ (r & 7)) << 4)));
}

__global__ __launch_bounds__(SA_THREADS, 1)
void simattn(const __half* __restrict__ cap, const __half* __restrict__ img,
             const int* __restrict__ lens, float* __restrict__ out)
{
    extern __shared__ char smem[];
    const uint32_t sbase = s2u(smem);
    float* SS   = (float*)(smem + OFF_SS);
    float* sinv = (float*)(smem + OFF_SINV);
    float* sW   = (float*)(smem + OFF_SW);
    float* wsum = (float*)(smem + OFF_WSUM);

    const int b    = blockIdx.x;
    const int tid  = threadIdx.x;
    const int warp = tid >> 5, lane = tid & 31;

    const __half* capb = cap + (size_t)b * NWORD * EMBED;
    const __half* imgb = img + (size_t)b * NREG  * EMBED;

    // my fixed row/chunks for loading + sumsq: row = tid>>1, chunks (tid&1)*4..+3
    const int myrow = tid >> 1;
    const int c0    = (tid & 1) * 4;
    const __half* growp = (myrow < NWORD) ? (capb + (size_t)myrow * EMBED)
                                          : (imgb + (size_t)(myrow - NWORD) * EMBED);

    // zero n-padding rows (96..111) of both buffers
    for (int idx = tid; idx < 2 * 16 * 8; idx += SA_THREADS) {
        int bf = idx >> 7, rem = idx & 127;
        int r = 96 + (rem >> 3), c = rem & 7;
        *(uint4*)(smem + OFF_BUF + bf * SA_BUF + soff_sa(r, c)) = make_uint4(0, 0, 0, 0);
    }

    auto load_slab = [&](int s, int bf) {
        const uint32_t sb = sbase + OFF_BUF + bf * SA_BUF;
        const __half* gp = growp + s * 64;
        #pragma unroll
        for (int i = 0; i < 4; i++)
            cp16(sb + soff_sa(myrow, c0 + i), gp + (c0 + i) * 8);
        CP_COMMIT();
    };

    float d[6][4];
    #pragma unroll
    for (int j = 0; j < 6; j++)
        #pragma unroll
        for (int q = 0; q < 4; q++) d[j][q] = 0.f;
    float sq = 0.f;

    load_slab(0, 0);

    for (int s = 0; s < SA_NSLAB; s++) {
        if (s + 1 < SA_NSLAB) {
            load_slab(s + 1, (s + 1) & 1);
            asm volatile("cp.async.wait_group 1;" ::: "memory");
        } else {
            asm volatile("cp.async.wait_group 0;" ::: "memory");
        }
        __syncthreads();
        const int bf = s & 1;
        const uint32_t sb = sbase + OFF_BUF + bf * SA_BUF;

        // per-thread row sumsq from hot smem
        #pragma unroll
        for (int i = 0; i < 4; i++) {
            uint4 v = *(uint4*)(smem + OFF_BUF + bf * SA_BUF + soff_sa(myrow, c0 + i));
            uint32_t w[4] = {v.x, v.y, v.z, v.w};
            #pragma unroll
            for (int q = 0; q < 4; q++) {
                float2 f = __half22float2(*(__half2*)&w[q]);
                sq += f.x * f.x + f.y * f.y;
            }
        }

        // MMA: warp w handles A rows [16w, 16w+16); B = rows 60..107 (3 x4-tiles)
        #pragma unroll
        for (int ks = 0; ks < 4; ks++) {
            const int ch = ks * 2 + (lane >> 4);
            uint32_t a[4];
            LDSM_X4(a[0], a[1], a[2], a[3], sb + soff_sa(warp * 16 + (lane & 15), ch));
            #pragma unroll
            for (int jb = 0; jb < 3; jb++) {
                uint32_t bb[4];
                LDSM_X4(bb[0], bb[1], bb[2], bb[3],
                        sb + soff_sa(60 + jb * 16 + (lane & 15), ch));
                MMA16816(d[2 * jb],     a, bb[0], bb[2]);
                MMA16816(d[2 * jb + 1], a, bb[1], bb[3]);
            }
        }
        __syncthreads();
    }

    // finalize norms: combine row halves (tid and tid^1 are same warp)
    float tot = sq + __shfl_xor_sync(0xffffffffu, sq, 1);
    if ((tid & 1) == 0) sinv[myrow] = tot;
    __syncthreads();
    if (tid < 112) sinv[tid] = (tid < 96) ? rsqrtf(sinv[tid] + 1e-12f) : 1.0f;
    __syncthreads();

    // write normalized S/G fragments to smem SS[96][50]
    {
        const int fr = lane >> 2;            // 0..7
        const int fc = (lane & 3) << 1;      // 0,2,..6
        #pragma unroll
        for (int jj = 0; jj < 6; jj++) {
            int col = jj * 8 + fc;
            float cn0 = sinv[60 + col], cn1 = sinv[60 + col + 1];
            int r0 = warp * 16 + fr;
            float rn0 = sinv[r0], rn1 = sinv[r0 + 8];
            SS[r0 * SSTRIDE + col]            = d[jj][0] * rn0 * cn0;
            SS[r0 * SSTRIDE + col + 1]        = d[jj][1] * rn0 * cn1;
            SS[(r0 + 8) * SSTRIDE + col]      = d[jj][2] * rn1 * cn0;
            SS[(r0 + 8) * SSTRIDE + col + 1]  = d[jj][3] * rn1 * cn1;
        }
    }
    __syncthreads();

    // ---- attention epilogue (6 warps over words) ----
    const int len = lens[b];
    float partial = 0.f;

    for (int l = warp; l < len; l += 6) {
        const float* sr = SS + l * SSTRIDE;
        float s0 = sr[lane];
        float s1 = (lane < 4) ? sr[lane + 32] : -1e30f;
        float m = fmaxf(s0, s1);
        #pragma unroll
        for (int o = 16; o > 0; o >>= 1) m = fmaxf(m, __shfl_xor_sync(0xffffffffu, m, o));

        float e0 = __expf(LAMBDA_SM * (s0 - m));
        float e1 = (lane < 4) ? __expf(LAMBDA_SM * (s1 - m)) : 0.f;
        float Z = e0 + e1;
        #pragma unroll
        for (int o = 16; o > 0; o >>= 1) Z += __shfl_xor_sync(0xffffffffu, Z, o);
        float inv = 1.f / Z;
        float w0 = e0 * inv;
        float w1 = e1 * inv;

        sW[warp * 40 + lane] = w0;
        if (lane < 4) sW[warp * 40 + lane + 32] = w1;
        __syncwarp();

        float num = w0 * s0 + ((lane < 4) ? w1 * s1 : 0.f);
        #pragma unroll
        for (int o = 16; o > 0; o >>= 1) num += __shfl_xor_sync(0xffffffffu, num, o);

        // den2 = w^T G w, G[r][r'] = SS[60+r][r']
        float t0 = 0.f;
        const float* gr0 = SS + (60 + lane) * SSTRIDE;
        #pragma unroll
        for (int rp = 0; rp < NREG; rp++) t0 += sW[warp * 40 + rp] * gr0[rp];
        float den2 = w0 * t0;
        if (lane < 4) {
            float t1 = 0.f;
            const float* gr1 = SS + (60 + lane + 32) * SSTRIDE;
            #pragma unroll
            for (int rp = 0; rp < NREG; rp++) t1 += sW[warp * 40 + rp] * gr1[rp];
            den2 += w1 * t1;
        }
        #pragma unroll
        for (int o = 16; o > 0; o >>= 1) den2 += __shfl_xor_sync(0xffffffffu, den2, o);

        float den = fmaxf(sqrtf(den2), 1e-8f);
        partial += num / den;
        __syncwarp();
    }

    if (lane == 0) wsum[warp] = partial;
    __syncthreads();
    if (tid == 0) {
        float t = 0.f;
        #pragma unroll
        for (int w = 0; w < 6; w++) t += wsum[w];
        out[b] = t / (float)len;
    }
}

// ---------------- launcher ----------------
extern "C" void kernel_launch(void* const* d_in, const int* in_sizes, int n_in,
                              void* d_out, int out_size)
{
    const float* images      = (const float*)d_in[0];
    const float* captions    = (const float*)d_in[1];
    const int*   cap_lengths = (const int*)  d_in[2];
    const float* W_img       = (const float*)d_in[3];
    const float* b_img       = (const float*)d_in[4];
    const float* W_txt       = (const float*)d_in[5];
    const float* b_txt       = (const float*)d_in[6];
    float* out = (float*)d_out;

    __half *img_embs, *cap_embs, *A16I, *A16C, *W16I, *W16T;
    cudaGetSymbolAddress((void**)&img_embs, g_img_embs);
    cudaGetSymbolAddress((void**)&cap_embs, g_cap_embs);
    cudaGetSymbolAddress((void**)&A16I, g_A16_img);
    cudaGetSymbolAddress((void**)&A16C, g_A16_cap);
    cudaGetSymbolAddress((void**)&W16I, g_W16_img);
    cudaGetSymbolAddress((void**)&W16T, g_W16_txt);

    cudaFuncSetAttribute(gemm_f16, cudaFuncAttributeMaxDynamicSharedMemorySize, GEMM_SMEM);
    cudaFuncSetAttribute(simattn,  cudaFuncAttributeMaxDynamicSharedMemorySize, SA_SMEM);

    // converts
    {
        int n4 = (M_IMG * IMG_DIM) / 4;
        cvt_f32_f16<<<(n4 + 255) / 256, 256>>>((const float4*)images, (__half2*)A16I, n4);
    }
    {
        int n4 = (IMG_DIM * EMBED) / 4;
        cvt_f32_f16<<<(n4 + 255) / 256, 256>>>((const float4*)W_img, (__half2*)W16I, n4);
    }
    cvt_pad_cap<<<(M_CAP * 80 + 255) / 256, 256>>>(captions, (__half2*)A16C);
    cvt_pad_wtxt<<<(KPAD_TXT * 256 + 255) / 256, 256>>>(W_txt, (__half2*)W16T);

    // tensor-core encoder GEMMs (f16 embedding output)
    gemm_f16<<<dim3(EMBED / GBN, M_IMG / GBM), 256, GEMM_SMEM>>>(
        A16I, W16I, b_img, img_embs, EMBED, IMG_DIM);
    gemm_f16<<<dim3(EMBED / GBN, M_CAP / GBM), 256, GEMM_SMEM>>>(
        A16C, W16T, b_txt, cap_embs, EMBED, KPAD_TXT);

    // fused sim + gram + norm + softmax + cosine + mean
    simattn<<<BATCH, SA_THREADS, SA_SMEM>>>(cap_embs, img_embs, cap_lengths, out);
}

// round 5
// speedup vs baseline: 6.5703x; 1.0634x over previous
#include <cuda_runtime.h>
#include <cuda_fp16.h>
#include <math.h>
#include <stdint.h>

// ---------------- problem constants ----------------
#define BATCH    256
#define NREG     36
#define NWORD    60
#define IMG_DIM  2048
#define WORD_DIM 300
#define KPAD_TXT 320
#define EMBED    1024
#define LAMBDA_SM 9.0f
#define M_IMG (BATCH*NREG)     // 9216
#define M_CAP (BATCH*NWORD)    // 15360

// ---------------- scratch (device globals; no allocation allowed) ----------------
__device__ __align__(256) __half g_img_embs[M_IMG * EMBED];
__device__ __align__(256) __half g_cap_embs[M_CAP * EMBED];

__device__ __align__(256) __half g_A16_img[M_IMG * IMG_DIM];
__device__ __align__(256) __half g_A16_cap[M_CAP * KPAD_TXT];
__device__ __align__(256) __half g_W16_img[IMG_DIM * EMBED];
__device__ __align__(256) __half g_W16_txt[KPAD_TXT * EMBED];

// ---------------- PTX helpers (sm_80-level only) ----------------
__device__ __forceinline__ uint32_t s2u(const void* p) {
    uint32_t a;
    asm("{ .reg .u64 t; cvta.to.shared.u64 t, %1; cvt.u32.u64 %0, t; }" : "=r"(a) : "l"(p));
    return a;
}
__device__ __forceinline__ void cp16(uint32_t s, const void* g) {
    asm volatile("cp.async.cg.shared.global [%0], [%1], 16;" :: "r"(s), "l"(g));
}
#define CP_COMMIT() asm volatile("cp.async.commit_group;" ::: "memory")

#define LDSM_X4(r0, r1, r2, r3, addr)                                            \
    asm volatile("ldmatrix.sync.aligned.m8n8.x4.shared.b16 {%0,%1,%2,%3}, [%4];" \
                 : "=r"(r0), "=r"(r1), "=r"(r2), "=r"(r3) : "r"(addr))
#define LDSM_X4_T(r0, r1, r2, r3, addr)                                          \
    asm volatile("ldmatrix.sync.aligned.m8n8.x4.trans.shared.b16 {%0,%1,%2,%3}, [%4];" \
                 : "=r"(r0), "=r"(r1), "=r"(r2), "=r"(r3) : "r"(addr))

#define MMA16816(d, a, b0, b1)                                                   \
    asm volatile("mma.sync.aligned.m16n8k16.row.col.f32.f16.f16.f32 "            \
                 "{%0,%1,%2,%3}, {%4,%5,%6,%7}, {%8,%9}, {%0,%1,%2,%3};"         \
                 : "+f"((d)[0]), "+f"((d)[1]), "+f"((d)[2]), "+f"((d)[3])        \
                 : "r"((a)[0]), "r"((a)[1]), "r"((a)[2]), "r"((a)[3]),           \
                   "r"(b0), "r"(b1))

// ---------------- single merged convert kernel ----------------
#define CVT_R0 ((M_IMG*IMG_DIM)/4)        // images f32->f16, 4-wide
#define CVT_R1 ((IMG_DIM*EMBED)/4)        // W_img  f32->f16, 4-wide
#define CVT_R2 (M_CAP*80)                 // captions pad to 320
#define CVT_R3 (KPAD_TXT*256)             // W_txt pad rows to 320
#define CVT_TOTAL (CVT_R0 + CVT_R1 + CVT_R2 + CVT_R3)

__global__ void cvt_all(const float* __restrict__ images, const float* __restrict__ W_img,
                        const float* __restrict__ captions, const float* __restrict__ W_txt,
                        __half2* __restrict__ A16I, __half2* __restrict__ W16I,
                        __half2* __restrict__ A16C, __half2* __restrict__ W16T)
{
    int idx = blockIdx.x * blockDim.x + threadIdx.x;
    if (idx < CVT_R0) {
        float4 v = ((const float4*)images)[idx];
        A16I[2 * idx]     = __floats2half2_rn(v.x, v.y);
        A16I[2 * idx + 1] = __floats2half2_rn(v.z, v.w);
        return;
    }
    idx -= CVT_R0;
    if (idx < CVT_R1) {
        float4 v = ((const float4*)W_img)[idx];
        W16I[2 * idx]     = __floats2half2_rn(v.x, v.y);
        W16I[2 * idx + 1] = __floats2half2_rn(v.z, v.w);
        return;
    }
    idx -= CVT_R1;
    if (idx < CVT_R2) {
        int row = idx / 80, g = idx - row * 80;
        __half2 h0, h1;
        if (g < 75) {
            float4 v = *(const float4*)(captions + (size_t)row * WORD_DIM + g * 4);
            h0 = __floats2half2_rn(v.x, v.y);
            h1 = __floats2half2_rn(v.z, v.w);
        } else {
            h0 = __floats2half2_rn(0.f, 0.f);
            h1 = h0;
        }
        size_t o = ((size_t)row * KPAD_TXT + g * 4) >> 1;
        A16C[o] = h0; A16C[o + 1] = h1;
        return;
    }
    idx -= CVT_R2;
    if (idx < CVT_R3) {
        int row = idx >> 8, g = idx & 255;
        __half2 h0, h1;
        if (row < WORD_DIM) {
            float4 v = *(const float4*)(W_txt + (size_t)row * EMBED + g * 4);
            h0 = __floats2half2_rn(v.x, v.y);
            h1 = __floats2half2_rn(v.z, v.w);
        } else {
            h0 = __floats2half2_rn(0.f, 0.f);
            h1 = h0;
        }
        size_t o = ((size_t)row * EMBED + g * 4) >> 1;
        W16T[o] = h0; W16T[o + 1] = h1;
    }
}

// ------------- merged fp16 TC GEMM: both problems in one launch -------------
// Tile 128x256, warp tile 64x64 (8 warps as 2m x 4n). 3-stage cp.async.
#define GBM 128
#define GBN 256
#define GBK 32
#define STAGES 3
#define STG_A 8192              // 128 x 32 f16
#define STG_B 16384             // 32 x 256 f16
#define STG_BYTES (STG_A + STG_B)
#define GEMM_SMEM (STAGES * STG_BYTES)   // 73728

#define IMG_BLKS ((M_IMG / GBM) * (EMBED / GBN))   // 72*4 = 288
#define CAP_BLKS ((M_CAP / GBM) * (EMBED / GBN))   // 120*4 = 480

__device__ __forceinline__ uint32_t aoff(int m, int u) {        // u = k/8 in [0,4)
    int blk  = m >> 1;
    int u128 = ((m & 1) << 2) | u;
    return (uint32_t)((blk << 7) + (((u128 ^ (blk & 7)) << 4)));
}
__device__ __forceinline__ uint32_t boff(int k, int j) {        // j = n/8 in [0,32)
    return (uint32_t)((k << 9) + ((j >> 3) << 7) + (((j & 7) ^ (k & 7)) << 4));
}

__global__ __launch_bounds__(256, 1)
void gemm_all(const __half* __restrict__ Aimg, const __half* __restrict__ Wimg,
              const float* __restrict__ bimg, __half* __restrict__ Cimg,
              const __half* __restrict__ Acap, const __half* __restrict__ Wcap,
              const float* __restrict__ bcap, __half* __restrict__ Ccap)
{
    extern __shared__ char smem[];
    const uint32_t sbase = s2u(smem);
    const int tid  = threadIdx.x;
    const int lane = tid & 31;
    const int wid  = tid >> 5;
    const int wm   = (wid & 1) * 64;
    const int wn   = (wid >> 1) * 64;
    const int N = EMBED;

    // decode problem / block
    const __half *A, *W;
    const float* bias;
    __half* C;
    int K, mb, nb;
    int bx = blockIdx.x;
    if (bx < IMG_BLKS) {
        A = Aimg; W = Wimg; bias = bimg; C = Cimg; K = IMG_DIM;
        mb = bx >> 2; nb = bx & 3;
    } else {
        bx -= IMG_BLKS;
        A = Acap; W = Wcap; bias = bcap; C = Ccap; K = KPAD_TXT;
        mb = bx >> 2; nb = bx & 3;
    }
    const int mbase = mb * GBM;
    const int nbase = nb * GBN;
    const int nk = K / GBK;

    float d[4][8][4];
    #pragma unroll
    for (int i = 0; i < 4; i++)
        #pragma unroll
        for (int j = 0; j < 8; j++)
            #pragma unroll
            for (int q = 0; q < 4; q++) d[i][j][q] = 0.f;

    auto load_slab = [&](int t, int st) {
        const uint32_t sA = sbase + st * STG_BYTES;
        const uint32_t sB = sA + STG_A;
        const int kb = t * GBK;
        #pragma unroll
        for (int i = 0; i < 2; i++) {            // A: 512 16B chunks
            int c = tid + i * 256;
            int m = c >> 2, u = c & 3;
            cp16(sA + aoff(m, u), A + (size_t)(mbase + m) * K + kb + u * 8);
        }
        #pragma unroll
        for (int i = 0; i < 4; i++) {            // B: 1024 16B chunks
            int c = tid + i * 256;
            int k = c >> 5, j = c & 31;
            cp16(sB + boff(k, j), W + (size_t)(kb + k) * N + nbase + j * 8);
        }
        CP_COMMIT();
    };

    load_slab(0, 0);
    load_slab(1, 1);

    for (int s = 0; s < nk; s++) {
        if (s + 1 < nk) asm volatile("cp.async.wait_group 1;" ::: "memory");
        else            asm volatile("cp.async.wait_group 0;" ::: "memory");
        __syncthreads();
        if (s + 2 < nk) load_slab(s + 2, (s + 2) % STAGES);

        const uint32_t sA = sbase + (s % STAGES) * STG_BYTES;
        const uint32_t sB = sA + STG_A;
        #pragma unroll
        for (int ks = 0; ks < 2; ks++) {
            uint32_t a[4][4], bb[4][4];
            #pragma unroll
            for (int mi = 0; mi < 4; mi++) {
                int m = wm + mi * 16 + (lane & 15);
                int u = ks * 2 + (lane >> 4);
                LDSM_X4(a[mi][0], a[mi][1], a[mi][2], a[mi][3], sA + aoff(m, u));
            }
            #pragma unroll
            for (int p = 0; p < 4; p++) {
                int k = ks * 16 + (lane & 7) + ((lane >> 3) & 1) * 8;
                int j = ((wn + p * 16) >> 3) + (lane >> 4);
                LDSM_X4_T(bb[p][0], bb[p][1], bb[p][2], bb[p][3], sB + boff(k, j));
            }
            #pragma unroll
            for (int mi = 0; mi < 4; mi++)
                #pragma unroll
                for (int nj = 0; nj < 8; nj++)
                    MMA16816(d[mi][nj], a[mi], bb[nj >> 1][(nj & 1) * 2],
                                               bb[nj >> 1][(nj & 1) * 2 + 1]);
        }
    }

    // epilogue: + bias, f16 store
    #pragma unroll
    for (int mi = 0; mi < 4; mi++) {
        int r0 = mbase + wm + mi * 16 + (lane >> 2);
        #pragma unroll
        for (int nj = 0; nj < 8; nj++) {
            int cc = nbase + wn + nj * 8 + ((lane & 3) << 1);
            float2 bv = *(const float2*)(bias + cc);
            *(__half2*)(C + (size_t)r0 * N + cc) =
                __floats2half2_rn(d[mi][nj][0] + bv.x, d[mi][nj][1] + bv.y);
            *(__half2*)(C + (size_t)(r0 + 8) * N + cc) =
                __floats2half2_rn(d[mi][nj][2] + bv.x, d[mi][nj][3] + bv.y);
        }
    }
}

// ---------------- fused sim + gram + l2norm + softmax + cosine + mean ----------------
#define SA_THREADS 192
#define SA_ROWS 112
#define SA_ROWB 128
#define SA_BUF (SA_ROWS * SA_ROWB)
#define SA_NSLAB 16
#define SSTRIDE 50
#define OFF_BUF  0
#define OFF_SS   (2 * SA_BUF)
#define OFF_SINV (OFF_SS + 96 * SSTRIDE * 4)
#define OFF_SW   (OFF_SINV + 112 * 4)
#define OFF_WSUM (OFF_SW + 6 * 40 * 4)
#define SA_SMEM  (OFF_WSUM + 32)

__device__ __forceinline__ uint32_t soff_sa(int r, int c) {
    return (uint32_t)(r * SA_ROWB + (((c ^ (r & 7)) << 4)));
}

__global__ __launch_bounds__(SA_THREADS, 1)
void simattn(const __half* __restrict__ cap, const __half* __restrict__ img,
             const int* __restrict__ lens, float* __restrict__ out)
{
    extern __shared__ char smem[];
    const uint32_t sbase = s2u(smem);
    float* SS   = (float*)(smem + OFF_SS);
    float* sinv = (float*)(smem + OFF_SINV);
    float* sW   = (float*)(smem + OFF_SW);
    float* wsum = (float*)(smem + OFF_WSUM);

    const int b    = blockIdx.x;
    const int tid  = threadIdx.x;
    const int warp = tid >> 5, lane = tid & 31;

    const __half* capb = cap + (size_t)b * NWORD * EMBED;
    const __half* imgb = img + (size_t)b * NREG  * EMBED;

    const int myrow = tid >> 1;
    const int c0    = (tid & 1) * 4;
    const __half* growp = (myrow < NWORD) ? (capb + (size_t)myrow * EMBED)
                                          : (imgb + (size_t)(myrow - NWORD) * EMBED);

    for (int idx = tid; idx < 2 * 16 * 8; idx += SA_THREADS) {
        int bf = idx >> 7, rem = idx & 127;
        int r = 96 + (rem >> 3), c = rem & 7;
        *(uint4*)(smem + OFF_BUF + bf * SA_BUF + soff_sa(r, c)) = make_uint4(0, 0, 0, 0);
    }

    auto load_slab = [&](int s, int bf) {
        const uint32_t sb = sbase + OFF_BUF + bf * SA_BUF;
        const __half* gp = growp + s * 64;
        #pragma unroll
        for (int i = 0; i < 4; i++)
            cp16(sb + soff_sa(myrow, c0 + i), gp + (c0 + i) * 8);
        CP_COMMIT();
    };

    float d[6][4];
    #pragma unroll
    for (int j = 0; j < 6; j++)
        #pragma unroll
        for (int q = 0; q < 4; q++) d[j][q] = 0.f;
    float sq = 0.f;

    load_slab(0, 0);

    for (int s = 0; s < SA_NSLAB; s++) {
        if (s + 1 < SA_NSLAB) {
            load_slab(s + 1, (s + 1) & 1);
            asm volatile("cp.async.wait_group 1;" ::: "memory");
        } else {
            asm volatile("cp.async.wait_group 0;" ::: "memory");
        }
        __syncthreads();
        const int bf = s & 1;
        const uint32_t sb = sbase + OFF_BUF + bf * SA_BUF;

        #pragma unroll
        for (int i = 0; i < 4; i++) {
            uint4 v = *(uint4*)(smem + OFF_BUF + bf * SA_BUF + soff_sa(myrow, c0 + i));
            uint32_t w[4] = {v.x, v.y, v.z, v.w};
            #pragma unroll
            for (int q = 0; q < 4; q++) {
                float2 f = __half22float2(*(__half2*)&w[q]);
                sq += f.x * f.x + f.y * f.y;
            }
        }

        #pragma unroll
        for (int ks = 0; ks < 4; ks++) {
            const int ch = ks * 2 + (lane >> 4);
            uint32_t a[4];
            LDSM_X4(a[0], a[1], a[2], a[3], sb + soff_sa(warp * 16 + (lane & 15), ch));
            #pragma unroll
            for (int jb = 0; jb < 3; jb++) {
                uint32_t bb[4];
                LDSM_X4(bb[0], bb[1], bb[2], bb[3],
                        sb + soff_sa(60 + jb * 16 + (lane & 15), ch));
                MMA16816(d[2 * jb],     a, bb[0], bb[2]);
                MMA16816(d[2 * jb + 1], a, bb[1], bb[3]);
            }
        }
        __syncthreads();
    }

    float tot = sq + __shfl_xor_sync(0xffffffffu, sq, 1);
    if ((tid & 1) == 0) sinv[myrow] = tot;
    __syncthreads();
    if (tid < 112) sinv[tid] = (tid < 96) ? rsqrtf(sinv[tid] + 1e-12f) : 1.0f;
    __syncthreads();

    {
        const int fr = lane >> 2;
        const int fc = (lane & 3) << 1;
        #pragma unroll
        for (int jj = 0; jj < 6; jj++) {
            int col = jj * 8 + fc;
            float cn0 = sinv[60 + col], cn1 = sinv[60 + col + 1];
            int r0 = warp * 16 + fr;
            float rn0 = sinv[r0], rn1 = sinv[r0 + 8];
            SS[r0 * SSTRIDE + col]            = d[jj][0] * rn0 * cn0;
            SS[r0 * SSTRIDE + col + 1]        = d[jj][1] * rn0 * cn1;
            SS[(r0 + 8) * SSTRIDE + col]      = d[jj][2] * rn1 * cn0;
            SS[(r0 + 8) * SSTRIDE + col + 1]  = d[jj][3] * rn1 * cn1;
        }
    }
    __syncthreads();

    const int len = lens[b];
    float partial = 0.f;

    for (int l = warp; l < len; l += 6) {
        const float* sr = SS + l * SSTRIDE;
        float s0 = sr[lane];
        float s1 = (lane < 4) ? sr[lane + 32] : -1e30f;
        float m = fmaxf(s0, s1);
        #pragma unroll
        for (int o = 16; o > 0; o >>= 1) m = fmaxf(m, __shfl_xor_sync(0xffffffffu, m, o));

        float e0 = __expf(LAMBDA_SM * (s0 - m));
        float e1 = (lane < 4) ? __expf(LAMBDA_SM * (s1 - m)) : 0.f;
        float Z = e0 + e1;
        #pragma unroll
        for (int o = 16; o > 0; o >>= 1) Z += __shfl_xor_sync(0xffffffffu, Z, o);
        float inv = 1.f / Z;
        float w0 = e0 * inv;
        float w1 = e1 * inv;

        sW[warp * 40 + lane] = w0;
        if (lane < 4) sW[warp * 40 + lane + 32] = w1;
        __syncwarp();

        float num = w0 * s0 + ((lane < 4) ? w1 * s1 : 0.f);
        #pragma unroll
        for (int o = 16; o > 0; o >>= 1) num += __shfl_xor_sync(0xffffffffu, num, o);

        float t0 = 0.f;
        const float* gr0 = SS + (60 + lane) * SSTRIDE;
        #pragma unroll
        for (int rp = 0; rp < NREG; rp++) t0 += sW[warp * 40 + rp] * gr0[rp];
        float den2 = w0 * t0;
        if (lane < 4) {
            float t1 = 0.f;
            const float* gr1 = SS + (60 + lane + 32) * SSTRIDE;
            #pragma unroll
            for (int rp = 0; rp < NREG; rp++) t1 += sW[warp * 40 + rp] * gr1[rp];
            den2 += w1 * t1;
        }
        #pragma unroll
        for (int o = 16; o > 0; o >>= 1) den2 += __shfl_xor_sync(0xffffffffu, den2, o);

        float den = fmaxf(sqrtf(den2), 1e-8f);
        partial += num / den;
        __syncwarp();
    }

    if (lane == 0) wsum[warp] = partial;
    __syncthreads();
    if (tid == 0) {
        float t = 0.f;
        #pragma unroll
        for (int w = 0; w < 6; w++) t += wsum[w];
        out[b] = t / (float)len;
    }
}

// ---------------- launcher ----------------
extern "C" void kernel_launch(void* const* d_in, const int* in_sizes, int n_in,
                              void* d_out, int out_size)
{
    const float* images      = (const float*)d_in[0];
    const float* captions    = (const float*)d_in[1];
    const int*   cap_lengths = (const int*)  d_in[2];
    const float* W_img       = (const float*)d_in[3];
    const float* b_img       = (const float*)d_in[4];
    const float* W_txt       = (const float*)d_in[5];
    const float* b_txt       = (const float*)d_in[6];
    float* out = (float*)d_out;

    __half *img_embs, *cap_embs, *A16I, *A16C, *W16I, *W16T;
    cudaGetSymbolAddress((void**)&img_embs, g_img_embs);
    cudaGetSymbolAddress((void**)&cap_embs, g_cap_embs);
    cudaGetSymbolAddress((void**)&A16I, g_A16_img);
    cudaGetSymbolAddress((void**)&A16C, g_A16_cap);
    cudaGetSymbolAddress((void**)&W16I, g_W16_img);
    cudaGetSymbolAddress((void**)&W16T, g_W16_txt);

    cudaFuncSetAttribute(gemm_all, cudaFuncAttributeMaxDynamicSharedMemorySize, GEMM_SMEM);
    cudaFuncSetAttribute(simattn,  cudaFuncAttributeMaxDynamicSharedMemorySize, SA_SMEM);

    // one merged convert launch
    cvt_all<<<CVT_TOTAL / 256, 256>>>(images, W_img, captions, W_txt,
                                      (__half2*)A16I, (__half2*)W16I,
                                      (__half2*)A16C, (__half2*)W16T);

    // one merged GEMM launch (img blocks first for balance)
    gemm_all<<<IMG_BLKS + CAP_BLKS, 256, GEMM_SMEM>>>(
        A16I, W16I, b_img, img_embs,
        A16C, W16T, b_txt, cap_embs);

    // fused sim + gram + norm + softmax + cosine + mean
    simattn<<<BATCH, SA_THREADS, SA_SMEM>>>(cap_embs, img_embs, cap_lengths, out);
}